// round 7
// baseline (speedup 1.0000x reference)
#include <cuda_runtime.h>

#define NN 8
#define CC 64
#define GG 8
#define DDp 16
#define HHs 56
#define WWs 56
#define HWsz (HHs*WWs)          /* 3136  */
#define DHWsz (DDp*HWsz)        /* 50176 */
#define CDHWsz (CC*DHWsz)       /* 3211264 */
#define OUT_ELEMS (NN*CDHWsz)   /* 25690112 */
#define OFF_ELEMS (NN*GG*DHWsz) /* 3211264 */
#define CNTf 401408.0f
#define XPU 72                  /* xs pitch in 8-byte dup-pair units; >=58 and ==8 mod 16 -> conflict-free */

typedef unsigned long long ull;

// ---------------- device scratch (no runtime allocation allowed) ----------------
__device__ float g_y1[OUT_ELEMS];          // deform conv output (pre-BN1)
__device__ float g_y2[OUT_ELEMS];          // conv2 output (pre-BN2)
__device__ float g_off[OFF_ELEMS];         // fallback offset buffer
__device__ float g_wT1[27*64*64];          // w1 transposed [tap][ci][co]
__device__ float g_wT2[27*64*64];          // w2 transposed [tap][ci][co]
__device__ float g_wToff[27*64*8];         // w_off transposed [tap][ci][gi]
__device__ float g_s1[64], g_q1[64], g_s2[64], g_q2[64];
__device__ float g_a1[64], g_b1[64], g_a2[64], g_b2[64];

// ---------------- f32x2 helpers ----------------
__device__ __forceinline__ ull pack2(float lo, float hi) {
    ull r; asm("mov.b64 %0, {%1, %2};" : "=l"(r) : "f"(lo), "f"(hi)); return r;
}
__device__ __forceinline__ void ffma2(ull& d, ull a, ull b) {
    asm("fma.rn.f32x2 %0, %1, %2, %0;" : "+l"(d) : "l"(a), "l"(b));
}

// ---------------- dummy (launch-index shim so ncu -s 5 lands on conv_main<0>) ----
__global__ void dummy_kernel() {}

// ---------------- prep: transpose weights, zero stats ----------------
__global__ void prep_kernel(const float* __restrict__ w_off,
                            const float* __restrict__ w1,
                            const float* __restrict__ w2) {
    int i = blockIdx.x * 256 + threadIdx.x;
    if (i < 27*4096) {
        int tap = i >> 12; int r = i & 4095; int ci = r >> 6; int co = r & 63;
        g_wT1[i] = w1[(co*64 + ci)*27 + tap];
        g_wT2[i] = w2[(co*64 + ci)*27 + tap];
    }
    if (i < 27*512) {
        int tap = i >> 9; int r = i & 511; int ci = r >> 3; int gi = r & 7;
        g_wToff[i] = w_off[(gi*64 + ci)*27 + tap];
    }
    if (i < 64) { g_s1[i]=0.f; g_q1[i]=0.f; g_s2[i]=0.f; g_q2[i]=0.f; }
}

// ---------------- conv1: offsets (Cout = 8) ----------------
// block: 256 thr; tile = 8 gi x 4h x 56w ; grid = N*D*14
__global__ __launch_bounds__(256, 2)
void conv_off_kernel(const float* __restrict__ x,
                     const float* __restrict__ b_off,
                     float* __restrict__ out_off) {
    extern __shared__ float sm[];
    float* xs = sm;                   // [64][6][64]
    float* ws = sm + 64*6*64;         // [2][512]
    const int tid = threadIdx.x;
    int b = blockIdx.x;
    const int ht = b % 14; b /= 14;
    const int d = b % DDp; const int n = b / DDp;
    const int h0 = ht * 4;
    const int hh_loc = tid / WWs;     // 0..3 (valid for tid<224)
    const int wq = tid % WWs;
    const bool active = tid < 224;

    float acc[8];
#pragma unroll
    for (int k = 0; k < 8; k++) acc[k] = 0.f;

    for (int i = tid; i < 512; i += 256) ws[i] = g_wToff[i];

    for (int kd = 0; kd < 3; kd++) {
        __syncthreads();
        const int dd = d + kd - 1;
        const bool vd = (unsigned)dd < DDp;
        const float* src = x + (size_t)n*CDHWsz + (size_t)dd*HWsz;
        for (int i = tid; i < 64*6*58; i += 256) {
            int wz = i % 58; int t = i / 58;
            int hr = t % 6;  int ci = t / 6;
            int hh = h0 - 1 + hr, ww = wz - 1;
            float v = 0.f;
            if (vd && (unsigned)hh < HHs && (unsigned)ww < WWs)
                v = src[(size_t)ci*DHWsz + hh*WWs + ww];
            xs[(ci*6 + hr)*64 + wz] = v;
        }
        __syncthreads();
        for (int t9 = 0; t9 < 9; t9++) {
            const int tap = kd*9 + t9;
            const float* wcur = ws + (tap & 1)*512;
            if (tap + 1 < 27) {
                float* wn = ws + ((tap + 1) & 1)*512;
                const float* s2 = g_wToff + (tap + 1)*512;
                for (int i = tid; i < 512; i += 256) wn[i] = s2[i];
            }
            const int kh = t9 / 3, kw = t9 - kh*3;
            if (active) {
                const float* xr = xs + (hh_loc + kh)*64 + wq + kw;
#pragma unroll 4
                for (int ci = 0; ci < 64; ci++) {
                    const float xv = xr[ci*6*64];
                    const float4 w0 = *(const float4*)(wcur + ci*8);
                    const float4 w1v = *(const float4*)(wcur + ci*8 + 4);
                    acc[0] = fmaf(xv, w0.x, acc[0]);
                    acc[1] = fmaf(xv, w0.y, acc[1]);
                    acc[2] = fmaf(xv, w0.z, acc[2]);
                    acc[3] = fmaf(xv, w0.w, acc[3]);
                    acc[4] = fmaf(xv, w1v.x, acc[4]);
                    acc[5] = fmaf(xv, w1v.y, acc[5]);
                    acc[6] = fmaf(xv, w1v.z, acc[6]);
                    acc[7] = fmaf(xv, w1v.w, acc[7]);
                }
            }
            __syncthreads();
        }
    }
    if (active) {
        const int h = h0 + hh_loc;
#pragma unroll
        for (int gi = 0; gi < 8; gi++)
            out_off[((size_t)(n*GG + gi)*DDp + d)*HWsz + h*WWs + wq] = acc[gi] + b_off[gi];
    }
}

// ---------------- main conv: MODE 0 = deform conv, MODE 1 = conv2 ----------------
// block: 256 thr = 16 co_t x 16 sp_t ; tile = 64 co x 2h x 56w ; grid = N*D*28
// x stored DUPLICATED as 8B (v,v) pairs (no pack MOVs in inner loop);
// 4 co/thread (2 f32x2 pairs): per (ci,kh) = 9 LDS.64 + 3 LDS.128 + 42 FFMA2.
// 16-ci phases; pitch 72 (>=58, ==8 mod 16) -> conflict-free.
template<int MODE>
__global__ __launch_bounds__(256, 2)
void conv_main(const float* __restrict__ xin,
               const float* __restrict__ offp,
               const float* __restrict__ bias) {
    extern __shared__ char smraw[];
    ull*   xs   = (ull*)smraw;                        // [16 ci][4 hr][XPU] dup pairs
    float* ws   = (float*)(smraw + 16*4*XPU*8);       // [16 ci][9 tap][64 co]
    float* offs = (float*)(smraw + 16*4*XPU*8 + 9216*4); // [8][4][64] (MODE 0)

    const int tid = threadIdx.x;
    const int co_t = tid >> 4, sp_t = tid & 15;   // warp = 2 co_t x 16 sp_t
    const int co0 = co_t * 4;
    const int hh_loc = sp_t >> 3;           // 0/1
    const int ww0 = (sp_t & 7) * 7;         // 0..49 — with pitch 72 all 16 lane addrs distinct mod 16
    int b = blockIdx.x;
    const int ht = b % 28; b /= 28;
    const int d = b % DDp; const int n = b / DDp;
    const int h0 = ht * 2;

    const float* wT = (MODE == 0) ? g_wT1 : g_wT2;

    // acc pairs: [j (7 outputs)][co-pair (2)], pair p holds (co0+2p, co0+2p+1)
    ull acc[14];
#pragma unroll
    for (int k = 0; k < 14; k++) acc[k] = 0ULL;

    if (MODE == 0) {
        for (int i = tid; i < 8*4*58; i += 256) {
            int wz = i % 58; int t = i / 58;
            int hr = t & 3;  int gi = t >> 2;
            int hh = h0 - 1 + hr, ww = wz - 1;
            float v = 0.f;
            if ((unsigned)hh < HHs && (unsigned)ww < WWs)
                v = offp[((size_t)(n*GG + gi)*DDp + d)*HWsz + hh*WWs + ww];
            offs[(gi*4 + hr)*64 + wz] = v;
        }
    }

    for (int kd = 0; kd < 3; kd++) {
        const int dd = d + kd - 1;
        const bool vd = (unsigned)dd < DDp;
        for (int phase = 0; phase < 4; phase++) {
            __syncthreads();      // prior compute done before xs/ws overwrite (covers offs 1st time)
            const int ci0 = phase * 16;
            // stage xs: 16 ci x 4 rows x 58 cols, stored as dup pairs (pitch XPU=72)
            for (int i = tid; i < 16*4*58; i += 256) {
                int wz = i % 58; int t = i / 58;
                int hr = t & 3;  int ci_l = t >> 2;
                const int ci = ci0 + ci_l;
                int hh = h0 - 1 + hr, ww = wz - 1;
                float v = 0.f;
                if ((unsigned)hh < HHs && (unsigned)ww < WWs) {
                    if (MODE == 0) {
                        // temporal deformable sampling: pos = d + off + (kd-1)
                        const float offv = offs[((ci >> 3)*4 + hr)*64 + wz];
                        const float pos = (offv + (float)d) + (float)(kd - 1);
                        const float f0 = floorf(pos);
                        const float frac = pos - f0;
                        const int i0 = (int)f0;
                        const float* base = xin + (size_t)n*CDHWsz + (size_t)ci*DHWsz + hh*WWs + ww;
                        const float v0 = ((unsigned)i0 < DDp) ? base[(size_t)i0*HWsz] : 0.f;
                        const float v1 = ((unsigned)(i0 + 1) < DDp) ? base[(size_t)(i0 + 1)*HWsz] : 0.f;
                        v = v0*(1.f - frac) + v1*frac;
                    } else {
                        if (vd) {
                            const float y = g_y1[(size_t)n*CDHWsz + (size_t)ci*DHWsz + (size_t)dd*HWsz + hh*WWs + ww];
                            v = fmaxf(fmaf(g_a1[ci], y, g_b1[ci]), 0.f);   // BN1 + ReLU fused
                        }
                    }
                }
                xs[(ci_l*4 + hr)*XPU + wz] = pack2(v, v);
            }
            // stage ws for same 16 ci
            for (int i = tid; i < 9216; i += 256) {
                const int co = i & 63;
                const int t9 = (i >> 6) % 9;
                const int ci_l = i / 576;
                ws[i] = wT[(size_t)(kd*9 + t9)*4096 + (ci0 + ci_l)*64 + co];
            }
            __syncthreads();      // xs+ws ready

#pragma unroll 2
            for (int ci_l = 0; ci_l < 16; ci_l++) {
                const ull* xbase = xs + (ci_l*4 + hh_loc)*XPU + ww0;
                const float* wrow = ws + ci_l*576 + co0;
#pragma unroll
                for (int kh = 0; kh < 3; kh++) {
                    ull xp[9];
                    const ull* xrow = xbase + kh*XPU;
#pragma unroll
                    for (int c = 0; c < 9; c++) xp[c] = xrow[c];
#pragma unroll
                    for (int kw = 0; kw < 3; kw++) {
                        const ulonglong2 wv = *(const ulonglong2*)(wrow + (kh*3 + kw)*64);
#pragma unroll
                        for (int j = 0; j < 7; j++) {
                            ffma2(acc[j*2+0], wv.x, xp[kw + j]);
                            ffma2(acc[j*2+1], wv.y, xp[kw + j]);
                        }
                    }
                }
            }
        }
    }

    // unpack, bias + store + fused BN stats
    float av[28];
#pragma unroll
    for (int j = 0; j < 7; j++) {
#pragma unroll
        for (int p = 0; p < 2; p++) {
            const float2 f = *(const float2*)&acc[j*2+p];
            av[j*4 + 2*p + 0] = f.x;
            av[j*4 + 2*p + 1] = f.y;
        }
    }
    float bv[4];
#pragma unroll
    for (int k = 0; k < 4; k++) bv[k] = (MODE == 1) ? bias[co0 + k] : 0.f;
    float* yout = (MODE == 0) ? g_y1 : g_y2;
    float s[4] = {0,0,0,0}, q[4] = {0,0,0,0};
    const int h = h0 + hh_loc;
#pragma unroll
    for (int j = 0; j < 7; j++) {
        const size_t base = (size_t)n*CDHWsz + (size_t)d*HWsz + h*WWs + (ww0 + j);
#pragma unroll
        for (int k = 0; k < 4; k++) {
            const float v = av[j*4+k] + bv[k];
            yout[base + (size_t)(co0 + k)*DHWsz] = v;
            s[k] += v; q[k] += v*v;
        }
    }
#pragma unroll
    for (int m = 1; m <= 8; m <<= 1) {
#pragma unroll
        for (int k = 0; k < 4; k++) {
            s[k] += __shfl_xor_sync(0xffffffffu, s[k], m);
            q[k] += __shfl_xor_sync(0xffffffffu, q[k], m);
        }
    }
    if (sp_t == 0) {
        float* gs = (MODE == 0) ? g_s1 : g_s2;
        float* gq = (MODE == 0) ? g_q1 : g_q2;
#pragma unroll
        for (int k = 0; k < 4; k++) {
            atomicAdd(&gs[co0 + k], s[k]);
            atomicAdd(&gq[co0 + k], q[k]);
        }
    }
}

// ---------------- BN finalize: a = gamma*rsqrt(var+eps), b = beta - a*mean ----------------
template<int WHICH>
__global__ void bn_finalize(const float* __restrict__ gamma, const float* __restrict__ beta) {
    const int c = threadIdx.x;
    const float* s = (WHICH == 0) ? g_s1 : g_s2;
    const float* q = (WHICH == 0) ? g_q1 : g_q2;
    float* a  = (WHICH == 0) ? g_a1 : g_a2;
    float* bo = (WHICH == 0) ? g_b1 : g_b2;
    const float mean = s[c] * (1.0f / CNTf);
    const float var  = q[c] * (1.0f / CNTf) - mean*mean;
    const float ai = gamma[c] * rsqrtf(var + 1e-5f);
    a[c] = ai;
    bo[c] = beta[c] - ai*mean;
}

// ---------------- epilogue: out = relu(bn2(y2) + x) ----------------
__global__ void finalize_out(const float* __restrict__ x, float* __restrict__ out) {
    const int i4 = blockIdx.x * blockDim.x + threadIdx.x;
    if (i4 >= OUT_ELEMS/4) return;
    const size_t i = (size_t)i4 * 4;
    const int c = (int)((i / DHWsz) & 63);
    const float a = g_a2[c], bb = g_b2[c];
    const float4 y  = *(const float4*)(g_y2 + i);
    const float4 xv = *(const float4*)(x + i);
    float4 r;
    r.x = fmaxf(fmaf(a, y.x, bb) + xv.x, 0.f);
    r.y = fmaxf(fmaf(a, y.y, bb) + xv.y, 0.f);
    r.z = fmaxf(fmaf(a, y.z, bb) + xv.z, 0.f);
    r.w = fmaxf(fmaf(a, y.w, bb) + xv.w, 0.f);
    *(float4*)(out + i) = r;
}

// ---------------- launch ----------------
extern "C" void kernel_launch(void* const* d_in, const int* in_sizes, int n_in,
                              void* d_out, int out_size) {
    const float* x     = (const float*)d_in[0];
    const float* w_off = (const float*)d_in[1];
    const float* b_off = (const float*)d_in[2];
    const float* w1    = (const float*)d_in[3];
    const float* w2    = (const float*)d_in[4];
    const float* b2    = (const float*)d_in[5];
    const float* g1    = (const float*)d_in[6];
    const float* be1   = (const float*)d_in[7];
    const float* g2    = (const float*)d_in[8];
    const float* be2   = (const float*)d_in[9];
    float* out = (float*)d_out;

    // off lives in d_out tail per tuple output (out, off); fall back to scratch if not.
    float* offdst = out + OUT_ELEMS;
    if (out_size < OUT_ELEMS + OFF_ELEMS) {
        void* p = nullptr;
        cudaGetSymbolAddress(&p, g_off);
        offdst = (float*)p;
    }

    const int SMEM_OFFK  = (64*6*64 + 2*512) * 4;                    // 102400
    const int SMEM_MAIN0 = 16*4*XPU*8 + 9216*4 + 8*4*64*4;           //  81920
    const int SMEM_MAIN1 = 16*4*XPU*8 + 9216*4;                      //  73728

    cudaFuncSetAttribute(conv_off_kernel, cudaFuncAttributeMaxDynamicSharedMemorySize, SMEM_OFFK);
    cudaFuncSetAttribute(conv_main<0>,    cudaFuncAttributeMaxDynamicSharedMemorySize, SMEM_MAIN0);
    cudaFuncSetAttribute(conv_main<1>,    cudaFuncAttributeMaxDynamicSharedMemorySize, SMEM_MAIN1);

    prep_kernel<<<432, 256>>>(w_off, w1, w2);          // idx 0
    conv_off_kernel<<<NN*DDp*14, 256, SMEM_OFFK>>>(x, b_off, offdst);  // idx 1
    dummy_kernel<<<1, 32>>>();                          // idx 2 (ncu shim)
    conv_main<0><<<NN*DDp*28, 256, SMEM_MAIN0>>>(x, offdst, b2);       // idx 3 <- ncu target
    bn_finalize<0><<<1, 64>>>(g1, be1);
    conv_main<1><<<NN*DDp*28, 256, SMEM_MAIN1>>>(x, offdst, b2);
    bn_finalize<1><<<1, 64>>>(g2, be2);
    finalize_out<<<(OUT_ELEMS/4 + 255)/256, 256>>>(x, out);
}

// round 8
// speedup vs baseline: 1.2053x; 1.2053x over previous
#include <cuda_runtime.h>

#define NN 8
#define CC 64
#define GG 8
#define DDp 16
#define HHs 56
#define WWs 56
#define HWsz (HHs*WWs)          /* 3136  */
#define DHWsz (DDp*HWsz)        /* 50176 */
#define CDHWsz (CC*DHWsz)       /* 3211264 */
#define OUT_ELEMS (NN*CDHWsz)   /* 25690112 */
#define OFF_ELEMS (NN*GG*DHWsz) /* 3211264 */
#define CNTf 401408.0f
#define XPU 36                  /* xs pitch (8B units); ==4 mod 16 -> 4h x 4w lanes conflict-free */

typedef unsigned long long ull;

// ---------------- device scratch (no runtime allocation allowed) ----------------
__device__ float g_y1[OUT_ELEMS];          // deform conv output (pre-BN1)
__device__ float g_y2[OUT_ELEMS];          // conv2 output (pre-BN2)
__device__ float g_off[OFF_ELEMS];         // fallback offset buffer
__device__ float g_wT1[27*64*64];          // w1 transposed [tap][ci][co]
__device__ float g_wT2[27*64*64];          // w2 transposed [tap][ci][co]
__device__ float g_wToff[27*64*8];         // w_off transposed [tap][ci][gi]
__device__ float g_s1[64], g_q1[64], g_s2[64], g_q2[64];
__device__ float g_a1[64], g_b1[64], g_a2[64], g_b2[64];

// ---------------- f32x2 helpers ----------------
__device__ __forceinline__ ull pack2(float lo, float hi) {
    ull r; asm("mov.b64 %0, {%1, %2};" : "=l"(r) : "f"(lo), "f"(hi)); return r;
}
__device__ __forceinline__ void ffma2(ull& d, ull a, ull b) {
    asm("fma.rn.f32x2 %0, %1, %2, %0;" : "+l"(d) : "l"(a), "l"(b));
}

// ---------------- dummy (launch-index shim so ncu -s 5 lands on conv_main<0>) ----
__global__ void dummy_kernel() {}

// ---------------- prep: transpose weights, zero stats ----------------
__global__ void prep_kernel(const float* __restrict__ w_off,
                            const float* __restrict__ w1,
                            const float* __restrict__ w2) {
    int i = blockIdx.x * 256 + threadIdx.x;
    if (i < 27*4096) {
        int tap = i >> 12; int r = i & 4095; int ci = r >> 6; int co = r & 63;
        g_wT1[i] = w1[(co*64 + ci)*27 + tap];
        g_wT2[i] = w2[(co*64 + ci)*27 + tap];
    }
    if (i < 27*512) {
        int tap = i >> 9; int r = i & 511; int ci = r >> 3; int gi = r & 7;
        g_wToff[i] = w_off[(gi*64 + ci)*27 + tap];
    }
    if (i < 64) { g_s1[i]=0.f; g_q1[i]=0.f; g_s2[i]=0.f; g_q2[i]=0.f; }
}

// ---------------- conv1: offsets (Cout = 8) ----------------
// block: 256 thr; tile = 8 gi x 4h x 56w ; grid = N*D*14
__global__ __launch_bounds__(256, 2)
void conv_off_kernel(const float* __restrict__ x,
                     const float* __restrict__ b_off,
                     float* __restrict__ out_off) {
    extern __shared__ float sm[];
    float* xs = sm;                   // [64][6][64]
    float* ws = sm + 64*6*64;         // [2][512]
    const int tid = threadIdx.x;
    int b = blockIdx.x;
    const int ht = b % 14; b /= 14;
    const int d = b % DDp; const int n = b / DDp;
    const int h0 = ht * 4;
    const int hh_loc = tid / WWs;     // 0..3 (valid for tid<224)
    const int wq = tid % WWs;
    const bool active = tid < 224;

    float acc[8];
#pragma unroll
    for (int k = 0; k < 8; k++) acc[k] = 0.f;

    for (int i = tid; i < 512; i += 256) ws[i] = g_wToff[i];

    for (int kd = 0; kd < 3; kd++) {
        __syncthreads();
        const int dd = d + kd - 1;
        const bool vd = (unsigned)dd < DDp;
        const float* src = x + (size_t)n*CDHWsz + (size_t)dd*HWsz;
        for (int i = tid; i < 64*6*58; i += 256) {
            int wz = i % 58; int t = i / 58;
            int hr = t % 6;  int ci = t / 6;
            int hh = h0 - 1 + hr, ww = wz - 1;
            float v = 0.f;
            if (vd && (unsigned)hh < HHs && (unsigned)ww < WWs)
                v = src[(size_t)ci*DHWsz + hh*WWs + ww];
            xs[(ci*6 + hr)*64 + wz] = v;
        }
        __syncthreads();
        for (int t9 = 0; t9 < 9; t9++) {
            const int tap = kd*9 + t9;
            const float* wcur = ws + (tap & 1)*512;
            if (tap + 1 < 27) {
                float* wn = ws + ((tap + 1) & 1)*512;
                const float* s2 = g_wToff + (tap + 1)*512;
                for (int i = tid; i < 512; i += 256) wn[i] = s2[i];
            }
            const int kh = t9 / 3, kw = t9 - kh*3;
            if (active) {
                const float* xr = xs + (hh_loc + kh)*64 + wq + kw;
#pragma unroll 4
                for (int ci = 0; ci < 64; ci++) {
                    const float xv = xr[ci*6*64];
                    const float4 w0 = *(const float4*)(wcur + ci*8);
                    const float4 w1v = *(const float4*)(wcur + ci*8 + 4);
                    acc[0] = fmaf(xv, w0.x, acc[0]);
                    acc[1] = fmaf(xv, w0.y, acc[1]);
                    acc[2] = fmaf(xv, w0.z, acc[2]);
                    acc[3] = fmaf(xv, w0.w, acc[3]);
                    acc[4] = fmaf(xv, w1v.x, acc[4]);
                    acc[5] = fmaf(xv, w1v.y, acc[5]);
                    acc[6] = fmaf(xv, w1v.z, acc[6]);
                    acc[7] = fmaf(xv, w1v.w, acc[7]);
                }
            }
            __syncthreads();
        }
    }
    if (active) {
        const int h = h0 + hh_loc;
#pragma unroll
        for (int gi = 0; gi < 8; gi++)
            out_off[((size_t)(n*GG + gi)*DDp + d)*HWsz + h*WWs + wq] = acc[gi] + b_off[gi];
    }
}

// ---------------- main conv: MODE 0 = deform conv, MODE 1 = conv2 ----------------
// block: 256 thr = 16 co_t x (4 hh x 4 wq) ; tile = 64 co x 4h x 28w ; grid = N*D*28
// 3 CTAs/SM (reg-dieted inner loop: sliding 3-wide x window, no pack MOVs).
// x stored DUPLICATED as 8B (v,v) pairs; pitch 36 -> conflict-free LDS.64.
template<int MODE>
__global__ __launch_bounds__(256, 3)
void conv_main(const float* __restrict__ xin,
               const float* __restrict__ offp,
               const float* __restrict__ bias) {
    extern __shared__ char smraw[];
    ull*   xs   = (ull*)smraw;                        // [16 ci][6 hr][XPU] dup pairs
    float* ws   = (float*)(smraw + 16*6*XPU*8);       // [16 ci][9 tap][64 co]
    float* offs = (float*)(smraw + 16*6*XPU*8 + 9216*4); // [8][6][30] (MODE 0)

    const int tid = threadIdx.x;
    const int co_t = tid >> 4, sp_t = tid & 15;
    const int co0 = co_t * 4;
    const int hh_loc = sp_t >> 2;           // 0..3
    const int ww0 = (sp_t & 3) * 7;         // 0,7,14,21
    int b = blockIdx.x;
    const int wt = b & 1; b >>= 1;
    const int ht = b % 14; b /= 14;
    const int d = b % DDp; const int n = b / DDp;
    const int h0 = ht * 4;
    const int w0 = wt * 28;

    const float* wT = (MODE == 0) ? g_wT1 : g_wT2;

    // acc pairs: [j (7 outputs)][co-pair (2)]
    ull acc[14];
#pragma unroll
    for (int k = 0; k < 14; k++) acc[k] = 0ULL;

    if (MODE == 0) {
        for (int i = tid; i < 8*6*30; i += 256) {
            int wz = i % 30; int t = i / 30;
            int hr = t % 6;  int gi = t / 6;
            int hh = h0 - 1 + hr, ww = w0 - 1 + wz;
            float v = 0.f;
            if ((unsigned)hh < HHs && (unsigned)ww < WWs)
                v = offp[((size_t)(n*GG + gi)*DDp + d)*HWsz + hh*WWs + ww];
            offs[(gi*6 + hr)*30 + wz] = v;
        }
    }

    for (int kd = 0; kd < 3; kd++) {
        const int dd = d + kd - 1;
        const bool vd = (unsigned)dd < DDp;
        for (int phase = 0; phase < 4; phase++) {
            __syncthreads();      // prior compute done before xs/ws overwrite (covers offs 1st time)
            const int ci0 = phase * 16;
            // stage xs: 16 ci x 6 rows x 30 cols, dup pairs, pitch XPU
            for (int i = tid; i < 16*6*30; i += 256) {
                int wz = i % 30; int t = i / 30;
                int hr = t % 6;  int ci_l = t / 6;
                const int ci = ci0 + ci_l;
                int hh = h0 - 1 + hr, ww = w0 - 1 + wz;
                float v = 0.f;
                if ((unsigned)hh < HHs && (unsigned)ww < WWs) {
                    if (MODE == 0) {
                        // temporal deformable sampling: pos = d + off + (kd-1)
                        const float offv = offs[((ci >> 3)*6 + hr)*30 + wz];
                        const float pos = (offv + (float)d) + (float)(kd - 1);
                        const float f0 = floorf(pos);
                        const float frac = pos - f0;
                        const int i0 = (int)f0;
                        const float* base = xin + (size_t)n*CDHWsz + (size_t)ci*DHWsz + hh*WWs + ww;
                        const float v0 = ((unsigned)i0 < DDp) ? base[(size_t)i0*HWsz] : 0.f;
                        const float v1 = ((unsigned)(i0 + 1) < DDp) ? base[(size_t)(i0 + 1)*HWsz] : 0.f;
                        v = v0*(1.f - frac) + v1*frac;
                    } else {
                        if (vd) {
                            const float y = g_y1[(size_t)n*CDHWsz + (size_t)ci*DHWsz + (size_t)dd*HWsz + hh*WWs + ww];
                            v = fmaxf(fmaf(g_a1[ci], y, g_b1[ci]), 0.f);   // BN1 + ReLU fused
                        }
                    }
                }
                xs[(ci_l*6 + hr)*XPU + wz] = pack2(v, v);
            }
            // stage ws for same 16 ci (vectorized float4)
            for (int i4 = tid; i4 < 2304; i4 += 256) {
                const int co4 = (i4 & 15) * 4;
                const int t9 = (i4 >> 4) % 9;
                const int ci_l = i4 / 144;
                const float4 wv4 = *(const float4*)(wT + (size_t)(kd*9 + t9)*4096 + (ci0 + ci_l)*64 + co4);
                *(float4*)(ws + ci_l*576 + t9*64 + co4) = wv4;
            }
            __syncthreads();      // xs+ws ready

            for (int ci_l = 0; ci_l < 16; ci_l++) {
                const ull* xbase = xs + (ci_l*6 + hh_loc)*XPU + ww0;
                const float* wrow = ws + ci_l*576 + co0;
#pragma unroll
                for (int kh = 0; kh < 3; kh++) {
                    const ulonglong2 wv0 = *(const ulonglong2*)(wrow + (kh*3 + 0)*64);
                    const ulonglong2 wv1 = *(const ulonglong2*)(wrow + (kh*3 + 1)*64);
                    const ulonglong2 wv2 = *(const ulonglong2*)(wrow + (kh*3 + 2)*64);
                    const ull* xrow = xbase + kh*XPU;
                    ull xa = xrow[0];
                    ull xb = xrow[1];
#pragma unroll
                    for (int j = 0; j < 7; j++) {
                        const ull xc = xrow[j + 2];
                        ffma2(acc[j*2+0], wv0.x, xa);
                        ffma2(acc[j*2+1], wv0.y, xa);
                        ffma2(acc[j*2+0], wv1.x, xb);
                        ffma2(acc[j*2+1], wv1.y, xb);
                        ffma2(acc[j*2+0], wv2.x, xc);
                        ffma2(acc[j*2+1], wv2.y, xc);
                        xa = xb; xb = xc;   // renamed by full unroll (no MOVs emitted)
                    }
                }
            }
        }
    }

    // unpack, bias + store + fused BN stats
    float bv[4];
#pragma unroll
    for (int k = 0; k < 4; k++) bv[k] = (MODE == 1) ? bias[co0 + k] : 0.f;
    float* yout = (MODE == 0) ? g_y1 : g_y2;
    float s[4] = {0,0,0,0}, q[4] = {0,0,0,0};
    const int h = h0 + hh_loc;
#pragma unroll
    for (int j = 0; j < 7; j++) {
        const size_t base = (size_t)n*CDHWsz + (size_t)d*HWsz + h*WWs + (w0 + ww0 + j);
#pragma unroll
        for (int p = 0; p < 2; p++) {
            const float2 f = *(const float2*)&acc[j*2+p];
            const float u0 = f.x + bv[2*p];
            const float u1 = f.y + bv[2*p+1];
            yout[base + (size_t)(co0 + 2*p)*DHWsz]     = u0;
            yout[base + (size_t)(co0 + 2*p + 1)*DHWsz] = u1;
            s[2*p] += u0;   q[2*p] += u0*u0;
            s[2*p+1] += u1; q[2*p+1] += u1*u1;
        }
    }
#pragma unroll
    for (int m = 1; m <= 8; m <<= 1) {
#pragma unroll
        for (int k = 0; k < 4; k++) {
            s[k] += __shfl_xor_sync(0xffffffffu, s[k], m);
            q[k] += __shfl_xor_sync(0xffffffffu, q[k], m);
        }
    }
    if (sp_t == 0) {
        float* gs = (MODE == 0) ? g_s1 : g_s2;
        float* gq = (MODE == 0) ? g_q1 : g_q2;
#pragma unroll
        for (int k = 0; k < 4; k++) {
            atomicAdd(&gs[co0 + k], s[k]);
            atomicAdd(&gq[co0 + k], q[k]);
        }
    }
}

// ---------------- BN finalize: a = gamma*rsqrt(var+eps), b = beta - a*mean ----------------
template<int WHICH>
__global__ void bn_finalize(const float* __restrict__ gamma, const float* __restrict__ beta) {
    const int c = threadIdx.x;
    const float* s = (WHICH == 0) ? g_s1 : g_s2;
    const float* q = (WHICH == 0) ? g_q1 : g_q2;
    float* a  = (WHICH == 0) ? g_a1 : g_a2;
    float* bo = (WHICH == 0) ? g_b1 : g_b2;
    const float mean = s[c] * (1.0f / CNTf);
    const float var  = q[c] * (1.0f / CNTf) - mean*mean;
    const float ai = gamma[c] * rsqrtf(var + 1e-5f);
    a[c] = ai;
    bo[c] = beta[c] - ai*mean;
}

// ---------------- epilogue: out = relu(bn2(y2) + x) ----------------
__global__ void finalize_out(const float* __restrict__ x, float* __restrict__ out) {
    const int i4 = blockIdx.x * blockDim.x + threadIdx.x;
    if (i4 >= OUT_ELEMS/4) return;
    const size_t i = (size_t)i4 * 4;
    const int c = (int)((i / DHWsz) & 63);
    const float a = g_a2[c], bb = g_b2[c];
    const float4 y  = *(const float4*)(g_y2 + i);
    const float4 xv = *(const float4*)(x + i);
    float4 r;
    r.x = fmaxf(fmaf(a, y.x, bb) + xv.x, 0.f);
    r.y = fmaxf(fmaf(a, y.y, bb) + xv.y, 0.f);
    r.z = fmaxf(fmaf(a, y.z, bb) + xv.z, 0.f);
    r.w = fmaxf(fmaf(a, y.w, bb) + xv.w, 0.f);
    *(float4*)(out + i) = r;
}

// ---------------- launch ----------------
extern "C" void kernel_launch(void* const* d_in, const int* in_sizes, int n_in,
                              void* d_out, int out_size) {
    const float* x     = (const float*)d_in[0];
    const float* w_off = (const float*)d_in[1];
    const float* b_off = (const float*)d_in[2];
    const float* w1    = (const float*)d_in[3];
    const float* w2    = (const float*)d_in[4];
    const float* b2    = (const float*)d_in[5];
    const float* g1    = (const float*)d_in[6];
    const float* be1   = (const float*)d_in[7];
    const float* g2    = (const float*)d_in[8];
    const float* be2   = (const float*)d_in[9];
    float* out = (float*)d_out;

    // off lives in d_out tail per tuple output (out, off); fall back to scratch if not.
    float* offdst = out + OUT_ELEMS;
    if (out_size < OUT_ELEMS + OFF_ELEMS) {
        void* p = nullptr;
        cudaGetSymbolAddress(&p, g_off);
        offdst = (float*)p;
    }

    const int SMEM_OFFK  = (64*6*64 + 2*512) * 4;                    // 102400
    const int SMEM_MAIN0 = 16*6*XPU*8 + 9216*4 + 8*6*30*4;           //  70272
    const int SMEM_MAIN1 = 16*6*XPU*8 + 9216*4;                      //  64512

    cudaFuncSetAttribute(conv_off_kernel, cudaFuncAttributeMaxDynamicSharedMemorySize, SMEM_OFFK);
    cudaFuncSetAttribute(conv_main<0>,    cudaFuncAttributeMaxDynamicSharedMemorySize, SMEM_MAIN0);
    cudaFuncSetAttribute(conv_main<1>,    cudaFuncAttributeMaxDynamicSharedMemorySize, SMEM_MAIN1);

    prep_kernel<<<432, 256>>>(w_off, w1, w2);          // idx 0
    conv_off_kernel<<<NN*DDp*14, 256, SMEM_OFFK>>>(x, b_off, offdst);  // idx 1
    dummy_kernel<<<1, 32>>>();                          // idx 2 (ncu shim)
    conv_main<0><<<NN*DDp*28, 256, SMEM_MAIN0>>>(x, offdst, b2);       // idx 3 <- ncu target
    bn_finalize<0><<<1, 64>>>(g1, be1);
    conv_main<1><<<NN*DDp*28, 256, SMEM_MAIN1>>>(x, offdst, b2);
    bn_finalize<1><<<1, 64>>>(g2, be2);
    finalize_out<<<(OUT_ELEMS/4 + 255)/256, 256>>>(x, out);
}

// round 10
// speedup vs baseline: 1.2116x; 1.0052x over previous
#include <cuda_runtime.h>

#define NN 8
#define CC 64
#define GG 8
#define DDp 16
#define HHs 56
#define WWs 56
#define HWsz (HHs*WWs)          /* 3136  */
#define DHWsz (DDp*HWsz)        /* 50176 */
#define CDHWsz (CC*DHWsz)       /* 3211264 */
#define OUT_ELEMS (NN*CDHWsz)   /* 25690112 */
#define OFF_ELEMS (NN*GG*DHWsz) /* 3211264 */
#define CNTf 401408.0f
#define XPU 36                  /* xs pitch (8B units); ==4 mod 16 -> 4h x 4w lanes conflict-free */

typedef unsigned long long ull;

// ---------------- device scratch (no runtime allocation allowed) ----------------
__device__ float g_y1[OUT_ELEMS];          // deform conv output (pre-BN1)
__device__ float g_y2[OUT_ELEMS];          // conv2 output (pre-BN2)
__device__ float g_off[OFF_ELEMS];         // fallback offset buffer
__device__ float g_wT1[27*64*64];          // w1 transposed [tap][ci][co]
__device__ float g_wT2[27*64*64];          // w2 transposed [tap][ci][co]
__device__ float g_wToff[27*64*8];         // w_off transposed [tap][ci][gi]
__device__ float g_s1[64], g_q1[64], g_s2[64], g_q2[64];
__device__ float g_a1[64], g_b1[64], g_a2[64], g_b2[64];

// ---------------- f32x2 helpers ----------------
__device__ __forceinline__ ull pack2(float lo, float hi) {
    ull r; asm("mov.b64 %0, {%1, %2};" : "=l"(r) : "f"(lo), "f"(hi)); return r;
}
__device__ __forceinline__ void ffma2(ull& d, ull a, ull b) {
    asm("fma.rn.f32x2 %0, %1, %2, %0;" : "+l"(d) : "l"(a), "l"(b));
}

// ---------------- dummy (launch-index shim so ncu -s 5 lands on conv_main<0>) ----
__global__ void dummy_kernel() {}

// ---------------- prep: transpose weights, zero stats ----------------
__global__ void prep_kernel(const float* __restrict__ w_off,
                            const float* __restrict__ w1,
                            const float* __restrict__ w2) {
    int i = blockIdx.x * 256 + threadIdx.x;
    if (i < 27*4096) {
        int tap = i >> 12; int r = i & 4095; int ci = r >> 6; int co = r & 63;
        g_wT1[i] = w1[(co*64 + ci)*27 + tap];
        g_wT2[i] = w2[(co*64 + ci)*27 + tap];
    }
    if (i < 27*512) {
        int tap = i >> 9; int r = i & 511; int ci = r >> 3; int gi = r & 7;
        g_wToff[i] = w_off[(gi*64 + ci)*27 + tap];
    }
    if (i < 64) { g_s1[i]=0.f; g_q1[i]=0.f; g_s2[i]=0.f; g_q2[i]=0.f; }
}

// ---------------- conv1: offsets (Cout = 8) ----------------
// block: 256 thr; tile = 8 gi x 4h x 56w ; grid = N*D*14
__global__ __launch_bounds__(256, 2)
void conv_off_kernel(const float* __restrict__ x,
                     const float* __restrict__ b_off,
                     float* __restrict__ out_off) {
    extern __shared__ float sm[];
    float* xs = sm;                   // [64][6][64]
    float* ws = sm + 64*6*64;         // [2][512]
    const int tid = threadIdx.x;
    int b = blockIdx.x;
    const int ht = b % 14; b /= 14;
    const int d = b % DDp; const int n = b / DDp;
    const int h0 = ht * 4;
    const int hh_loc = tid / WWs;     // 0..3 (valid for tid<224)
    const int wq = tid % WWs;
    const bool active = tid < 224;

    float acc[8];
#pragma unroll
    for (int k = 0; k < 8; k++) acc[k] = 0.f;

    for (int i = tid; i < 512; i += 256) ws[i] = g_wToff[i];

    for (int kd = 0; kd < 3; kd++) {
        __syncthreads();
        const int dd = d + kd - 1;
        const bool vd = (unsigned)dd < DDp;
        const float* src = x + (size_t)n*CDHWsz + (size_t)dd*HWsz;
        for (int i = tid; i < 64*6*58; i += 256) {
            int wz = i % 58; int t = i / 58;
            int hr = t % 6;  int ci = t / 6;
            int hh = h0 - 1 + hr, ww = wz - 1;
            float v = 0.f;
            if (vd && (unsigned)hh < HHs && (unsigned)ww < WWs)
                v = src[(size_t)ci*DHWsz + hh*WWs + ww];
            xs[(ci*6 + hr)*64 + wz] = v;
        }
        __syncthreads();
        for (int t9 = 0; t9 < 9; t9++) {
            const int tap = kd*9 + t9;
            const float* wcur = ws + (tap & 1)*512;
            if (tap + 1 < 27) {
                float* wn = ws + ((tap + 1) & 1)*512;
                const float* s2 = g_wToff + (tap + 1)*512;
                for (int i = tid; i < 512; i += 256) wn[i] = s2[i];
            }
            const int kh = t9 / 3, kw = t9 - kh*3;
            if (active) {
                const float* xr = xs + (hh_loc + kh)*64 + wq + kw;
#pragma unroll 4
                for (int ci = 0; ci < 64; ci++) {
                    const float xv = xr[ci*6*64];
                    const float4 w0 = *(const float4*)(wcur + ci*8);
                    const float4 w1v = *(const float4*)(wcur + ci*8 + 4);
                    acc[0] = fmaf(xv, w0.x, acc[0]);
                    acc[1] = fmaf(xv, w0.y, acc[1]);
                    acc[2] = fmaf(xv, w0.z, acc[2]);
                    acc[3] = fmaf(xv, w0.w, acc[3]);
                    acc[4] = fmaf(xv, w1v.x, acc[4]);
                    acc[5] = fmaf(xv, w1v.y, acc[5]);
                    acc[6] = fmaf(xv, w1v.z, acc[6]);
                    acc[7] = fmaf(xv, w1v.w, acc[7]);
                }
            }
            __syncthreads();
        }
    }
    if (active) {
        const int h = h0 + hh_loc;
#pragma unroll
        for (int gi = 0; gi < 8; gi++)
            out_off[((size_t)(n*GG + gi)*DDp + d)*HWsz + h*WWs + wq] = acc[gi] + b_off[gi];
    }
}

// ---------------- main conv: MODE 0 = deform conv, MODE 1 = conv2 ----------------
// block: 256 thr = 16 co_t x (4 hh x 4 wq) ; tile = 64 co x 4h x 28w ; grid = N*D*28
// 3 CTAs/SM; flattened (kd,phase) loop ROTATED per CTA wave so co-resident CTAs'
// staging windows overlap other CTAs' compute (fp32 sum reorder only).
template<int MODE>
__global__ __launch_bounds__(256, 3)
void conv_main(const float* __restrict__ xin,
               const float* __restrict__ offp,
               const float* __restrict__ bias) {
    extern __shared__ char smraw[];
    ull*   xs   = (ull*)smraw;                        // [16 ci][6 hr][XPU] dup pairs
    float* ws   = (float*)(smraw + 16*6*XPU*8);       // [16 ci][9 tap][64 co]
    float* offs = (float*)(smraw + 16*6*XPU*8 + 9216*4); // [8][6][30] (MODE 0)

    const int tid = threadIdx.x;
    const int co_t = tid >> 4, sp_t = tid & 15;
    const int co0 = co_t * 4;
    const int hh_loc = sp_t >> 2;           // 0..3
    const int ww0 = (sp_t & 3) * 7;         // 0,7,14,21
    const int bid = blockIdx.x;
    int b = bid;
    const int wt = b & 1; b >>= 1;
    const int ht = b % 14; b /= 14;
    const int d = b % DDp; const int n = b / DDp;
    const int h0 = ht * 4;
    const int w0 = wt * 28;
    // co-resident CTAs (consecutive waves of 148) start 4 phases apart
    const int rot = ((bid / 148) % 3) * 4;

    const float* wT = (MODE == 0) ? g_wT1 : g_wT2;

    // acc pairs: [j (7 outputs)][co-pair (2)]
    ull acc[14];
#pragma unroll
    for (int k = 0; k < 14; k++) acc[k] = 0ULL;

    if (MODE == 0) {
        for (int i = tid; i < 8*6*30; i += 256) {
            int wz = i % 30; int t = i / 30;
            int hr = t % 6;  int gi = t / 6;
            int hh = h0 - 1 + hr, ww = w0 - 1 + wz;
            float v = 0.f;
            if ((unsigned)hh < HHs && (unsigned)ww < WWs)
                v = offp[((size_t)(n*GG + gi)*DDp + d)*HWsz + hh*WWs + ww];
            offs[(gi*6 + hr)*30 + wz] = v;
        }
    }

    for (int it = 0; it < 12; it++) {
        int idx = it + rot; if (idx >= 12) idx -= 12;
        const int kd = idx >> 2;           // 0..2
        const int phase = idx & 3;         // 0..3
        const int dd = d + kd - 1;
        const bool vd = (unsigned)dd < DDp;
        __syncthreads();      // prior compute done before xs/ws overwrite (covers offs 1st time)
        const int ci0 = phase * 16;
        // stage xs: 16 ci x 6 rows x 30 cols, dup pairs, pitch XPU
        for (int i = tid; i < 16*6*30; i += 256) {
            int wz = i % 30; int t = i / 30;
            int hr = t % 6;  int ci_l = t / 6;
            const int ci = ci0 + ci_l;
            int hh = h0 - 1 + hr, ww = w0 - 1 + wz;
            float v = 0.f;
            if ((unsigned)hh < HHs && (unsigned)ww < WWs) {
                if (MODE == 0) {
                    // temporal deformable sampling: pos = d + off + (kd-1)
                    const float offv = offs[((ci >> 3)*6 + hr)*30 + wz];
                    const float pos = (offv + (float)d) + (float)(kd - 1);
                    const float f0 = floorf(pos);
                    const float frac = pos - f0;
                    const int i0 = (int)f0;
                    const float* base = xin + (size_t)n*CDHWsz + (size_t)ci*DHWsz + hh*WWs + ww;
                    const float v0 = ((unsigned)i0 < DDp) ? base[(size_t)i0*HWsz] : 0.f;
                    const float v1 = ((unsigned)(i0 + 1) < DDp) ? base[(size_t)(i0 + 1)*HWsz] : 0.f;
                    v = v0*(1.f - frac) + v1*frac;
                } else {
                    if (vd) {
                        const float y = g_y1[(size_t)n*CDHWsz + (size_t)ci*DHWsz + (size_t)dd*HWsz + hh*WWs + ww];
                        v = fmaxf(fmaf(g_a1[ci], y, g_b1[ci]), 0.f);   // BN1 + ReLU fused
                    }
                }
            }
            xs[(ci_l*6 + hr)*XPU + wz] = pack2(v, v);
        }
        // stage ws for same 16 ci (vectorized float4)
        for (int i4 = tid; i4 < 2304; i4 += 256) {
            const int co4 = (i4 & 15) * 4;
            const int t9 = (i4 >> 4) % 9;
            const int ci_l = i4 / 144;
            const float4 wv4 = *(const float4*)(wT + (size_t)(kd*9 + t9)*4096 + (ci0 + ci_l)*64 + co4);
            *(float4*)(ws + ci_l*576 + t9*64 + co4) = wv4;
        }
        __syncthreads();      // xs+ws ready

        for (int ci_l = 0; ci_l < 16; ci_l++) {
            const ull* xbase = xs + (ci_l*6 + hh_loc)*XPU + ww0;
            const float* wrow = ws + ci_l*576 + co0;
#pragma unroll
            for (int kh = 0; kh < 3; kh++) {
                const ulonglong2 wv0 = *(const ulonglong2*)(wrow + (kh*3 + 0)*64);
                const ulonglong2 wv1 = *(const ulonglong2*)(wrow + (kh*3 + 1)*64);
                const ulonglong2 wv2 = *(const ulonglong2*)(wrow + (kh*3 + 2)*64);
                const ull* xrow = xbase + kh*XPU;
                ull xa = xrow[0];
                ull xb = xrow[1];
#pragma unroll
                for (int j = 0; j < 7; j++) {
                    const ull xc = xrow[j + 2];
                    ffma2(acc[j*2+0], wv0.x, xa);
                    ffma2(acc[j*2+1], wv0.y, xa);
                    ffma2(acc[j*2+0], wv1.x, xb);
                    ffma2(acc[j*2+1], wv1.y, xb);
                    ffma2(acc[j*2+0], wv2.x, xc);
                    ffma2(acc[j*2+1], wv2.y, xc);
                    xa = xb; xb = xc;   // renamed by full unroll (no MOVs emitted)
                }
            }
        }
    }

    // unpack, bias + store + fused BN stats
    float bv[4];
#pragma unroll
    for (int k = 0; k < 4; k++) bv[k] = (MODE == 1) ? bias[co0 + k] : 0.f;
    float* yout = (MODE == 0) ? g_y1 : g_y2;
    float s[4] = {0,0,0,0}, q[4] = {0,0,0,0};
    const int h = h0 + hh_loc;
#pragma unroll
    for (int j = 0; j < 7; j++) {
        const size_t base = (size_t)n*CDHWsz + (size_t)d*HWsz + h*WWs + (w0 + ww0 + j);
#pragma unroll
        for (int p = 0; p < 2; p++) {
            const float2 f = *(const float2*)&acc[j*2+p];
            const float u0 = f.x + bv[2*p];
            const float u1 = f.y + bv[2*p+1];
            yout[base + (size_t)(co0 + 2*p)*DHWsz]     = u0;
            yout[base + (size_t)(co0 + 2*p + 1)*DHWsz] = u1;
            s[2*p] += u0;   q[2*p] += u0*u0;
            s[2*p+1] += u1; q[2*p+1] += u1*u1;
        }
    }
#pragma unroll
    for (int m = 1; m <= 8; m <<= 1) {
#pragma unroll
        for (int k = 0; k < 4; k++) {
            s[k] += __shfl_xor_sync(0xffffffffu, s[k], m);
            q[k] += __shfl_xor_sync(0xffffffffu, q[k], m);
        }
    }
    if (sp_t == 0) {
        float* gs = (MODE == 0) ? g_s1 : g_s2;
        float* gq = (MODE == 0) ? g_q1 : g_q2;
#pragma unroll
        for (int k = 0; k < 4; k++) {
            atomicAdd(&gs[co0 + k], s[k]);
            atomicAdd(&gq[co0 + k], q[k]);
        }
    }
}

// ---------------- BN finalize: a = gamma*rsqrt(var+eps), b = beta - a*mean ----------------
template<int WHICH>
__global__ void bn_finalize(const float* __restrict__ gamma, const float* __restrict__ beta) {
    const int c = threadIdx.x;
    const float* s = (WHICH == 0) ? g_s1 : g_s2;
    const float* q = (WHICH == 0) ? g_q1 : g_q2;
    float* a  = (WHICH == 0) ? g_a1 : g_a2;
    float* bo = (WHICH == 0) ? g_b1 : g_b2;
    const float mean = s[c] * (1.0f / CNTf);
    const float var  = q[c] * (1.0f / CNTf) - mean*mean;
    const float ai = gamma[c] * rsqrtf(var + 1e-5f);
    a[c] = ai;
    bo[c] = beta[c] - ai*mean;
}

// ---------------- epilogue: out = relu(bn2(y2) + x) ----------------
__global__ void finalize_out(const float* __restrict__ x, float* __restrict__ out) {
    const int i4 = blockIdx.x * blockDim.x + threadIdx.x;
    if (i4 >= OUT_ELEMS/4) return;
    const size_t i = (size_t)i4 * 4;
    const int c = (int)((i / DHWsz) & 63);
    const float a = g_a2[c], bb = g_b2[c];
    const float4 y  = *(const float4*)(g_y2 + i);
    const float4 xv = *(const float4*)(x + i);
    float4 r;
    r.x = fmaxf(fmaf(a, y.x, bb) + xv.x, 0.f);
    r.y = fmaxf(fmaf(a, y.y, bb) + xv.y, 0.f);
    r.z = fmaxf(fmaf(a, y.z, bb) + xv.z, 0.f);
    r.w = fmaxf(fmaf(a, y.w, bb) + xv.w, 0.f);
    *(float4*)(out + i) = r;
}

// ---------------- launch ----------------
extern "C" void kernel_launch(void* const* d_in, const int* in_sizes, int n_in,
                              void* d_out, int out_size) {
    const float* x     = (const float*)d_in[0];
    const float* w_off = (const float*)d_in[1];
    const float* b_off = (const float*)d_in[2];
    const float* w1    = (const float*)d_in[3];
    const float* w2    = (const float*)d_in[4];
    const float* b2    = (const float*)d_in[5];
    const float* g1    = (const float*)d_in[6];
    const float* be1   = (const float*)d_in[7];
    const float* g2    = (const float*)d_in[8];
    const float* be2   = (const float*)d_in[9];
    float* out = (float*)d_out;

    // off lives in d_out tail per tuple output (out, off); fall back to scratch if not.
    float* offdst = out + OUT_ELEMS;
    if (out_size < OUT_ELEMS + OFF_ELEMS) {
        void* p = nullptr;
        cudaGetSymbolAddress(&p, g_off);
        offdst = (float*)p;
    }

    const int SMEM_OFFK  = (64*6*64 + 2*512) * 4;                    // 102400
    const int SMEM_MAIN0 = 16*6*XPU*8 + 9216*4 + 8*6*30*4;           //  70272
    const int SMEM_MAIN1 = 16*6*XPU*8 + 9216*4;                      //  64512

    cudaFuncSetAttribute(conv_off_kernel, cudaFuncAttributeMaxDynamicSharedMemorySize, SMEM_OFFK);
    cudaFuncSetAttribute(conv_main<0>,    cudaFuncAttributeMaxDynamicSharedMemorySize, SMEM_MAIN0);
    cudaFuncSetAttribute(conv_main<1>,    cudaFuncAttributeMaxDynamicSharedMemorySize, SMEM_MAIN1);

    prep_kernel<<<432, 256>>>(w_off, w1, w2);          // idx 0
    conv_off_kernel<<<NN*DDp*14, 256, SMEM_OFFK>>>(x, b_off, offdst);  // idx 1
    dummy_kernel<<<1, 32>>>();                          // idx 2 (ncu shim)
    conv_main<0><<<NN*DDp*28, 256, SMEM_MAIN0>>>(x, offdst, b2);       // idx 3 <- ncu target
    bn_finalize<0><<<1, 64>>>(g1, be1);
    conv_main<1><<<NN*DDp*28, 256, SMEM_MAIN1>>>(x, offdst, b2);
    bn_finalize<1><<<1, 64>>>(g2, be2);
    finalize_out<<<(OUT_ELEMS/4 + 255)/256, 256>>>(x, out);
}

// round 12
// speedup vs baseline: 1.2319x; 1.0167x over previous
#include <cuda_runtime.h>

#define NN 8
#define CC 64
#define GG 8
#define DDp 16
#define HHs 56
#define WWs 56
#define HWsz (HHs*WWs)          /* 3136  */
#define DHWsz (DDp*HWsz)        /* 50176 */
#define CDHWsz (CC*DHWsz)       /* 3211264 */
#define OUT_ELEMS (NN*CDHWsz)   /* 25690112 */
#define OFF_ELEMS (NN*GG*DHWsz) /* 3211264 */
#define CNTf 401408.0f
#define XPU 60                  /* xs pitch (8B units); ==12 mod 16 -> 4h x 8w lanes conflict-free */

typedef unsigned long long ull;

// ---------------- device scratch (no runtime allocation allowed) ----------------
__device__ float g_y1[OUT_ELEMS];          // deform conv output (pre-BN1)
__device__ float g_y2[OUT_ELEMS];          // conv2 output (pre-BN2)
__device__ float g_off[OFF_ELEMS];         // fallback offset buffer
__device__ float g_wT1[27*64*64];          // w1 transposed [tap][ci][co]
__device__ float g_wT2[27*64*64];          // w2 transposed [tap][ci][co]
__device__ float g_wToff[27*64*8];         // w_off transposed [tap][ci][gi]
__device__ float g_s1[64], g_q1[64], g_s2[64], g_q2[64];
__device__ float g_a1[64], g_b1[64], g_a2[64], g_b2[64];

// ---------------- f32x2 helpers ----------------
__device__ __forceinline__ ull pack2(float lo, float hi) {
    ull r; asm("mov.b64 %0, {%1, %2};" : "=l"(r) : "f"(lo), "f"(hi)); return r;
}
__device__ __forceinline__ void ffma2(ull& d, ull a, ull b) {
    asm("fma.rn.f32x2 %0, %1, %2, %0;" : "+l"(d) : "l"(a), "l"(b));
}

// ---------------- dummy (launch-index shim so ncu -s 5 lands on conv_main<0>) ----
__global__ void dummy_kernel() {}

// ---------------- prep: transpose weights, zero stats ----------------
__global__ void prep_kernel(const float* __restrict__ w_off,
                            const float* __restrict__ w1,
                            const float* __restrict__ w2) {
    int i = blockIdx.x * 256 + threadIdx.x;
    if (i < 27*4096) {
        int tap = i >> 12; int r = i & 4095; int ci = r >> 6; int co = r & 63;
        g_wT1[i] = w1[(co*64 + ci)*27 + tap];
        g_wT2[i] = w2[(co*64 + ci)*27 + tap];
    }
    if (i < 27*512) {
        int tap = i >> 9; int r = i & 511; int ci = r >> 3; int gi = r & 7;
        g_wToff[i] = w_off[(gi*64 + ci)*27 + tap];
    }
    if (i < 64) { g_s1[i]=0.f; g_q1[i]=0.f; g_s2[i]=0.f; g_q2[i]=0.f; }
}

// ---------------- conv1: offsets (Cout = 8) ----------------
// block: 256 thr; tile = 8 gi x 4h x 56w ; grid = N*D*14
__global__ __launch_bounds__(256, 2)
void conv_off_kernel(const float* __restrict__ x,
                     const float* __restrict__ b_off,
                     float* __restrict__ out_off) {
    extern __shared__ float sm[];
    float* xs = sm;                   // [64][6][64]
    float* ws = sm + 64*6*64;         // [2][512]
    const int tid = threadIdx.x;
    int b = blockIdx.x;
    const int ht = b % 14; b /= 14;
    const int d = b % DDp; const int n = b / DDp;
    const int h0 = ht * 4;
    const int hh_loc = tid / WWs;     // 0..3 (valid for tid<224)
    const int wq = tid % WWs;
    const bool active = tid < 224;

    float acc[8];
#pragma unroll
    for (int k = 0; k < 8; k++) acc[k] = 0.f;

    for (int i = tid; i < 512; i += 256) ws[i] = g_wToff[i];

    for (int kd = 0; kd < 3; kd++) {
        __syncthreads();
        const int dd = d + kd - 1;
        const bool vd = (unsigned)dd < DDp;
        const float* src = x + (size_t)n*CDHWsz + (size_t)dd*HWsz;
        for (int i = tid; i < 64*6*58; i += 256) {
            int wz = i % 58; int t = i / 58;
            int hr = t % 6;  int ci = t / 6;
            int hh = h0 - 1 + hr, ww = wz - 1;
            float v = 0.f;
            if (vd && (unsigned)hh < HHs && (unsigned)ww < WWs)
                v = src[(size_t)ci*DHWsz + hh*WWs + ww];
            xs[(ci*6 + hr)*64 + wz] = v;
        }
        __syncthreads();
        for (int t9 = 0; t9 < 9; t9++) {
            const int tap = kd*9 + t9;
            const float* wcur = ws + (tap & 1)*512;
            if (tap + 1 < 27) {
                float* wn = ws + ((tap + 1) & 1)*512;
                const float* s2 = g_wToff + (tap + 1)*512;
                for (int i = tid; i < 512; i += 256) wn[i] = s2[i];
            }
            const int kh = t9 / 3, kw = t9 - kh*3;
            if (active) {
                const float* xr = xs + (hh_loc + kh)*64 + wq + kw;
#pragma unroll 4
                for (int ci = 0; ci < 64; ci++) {
                    const float xv = xr[ci*6*64];
                    const float4 w0 = *(const float4*)(wcur + ci*8);
                    const float4 w1v = *(const float4*)(wcur + ci*8 + 4);
                    acc[0] = fmaf(xv, w0.x, acc[0]);
                    acc[1] = fmaf(xv, w0.y, acc[1]);
                    acc[2] = fmaf(xv, w0.z, acc[2]);
                    acc[3] = fmaf(xv, w0.w, acc[3]);
                    acc[4] = fmaf(xv, w1v.x, acc[4]);
                    acc[5] = fmaf(xv, w1v.y, acc[5]);
                    acc[6] = fmaf(xv, w1v.z, acc[6]);
                    acc[7] = fmaf(xv, w1v.w, acc[7]);
                }
            }
            __syncthreads();
        }
    }
    if (active) {
        const int h = h0 + hh_loc;
#pragma unroll
        for (int gi = 0; gi < 8; gi++)
            out_off[((size_t)(n*GG + gi)*DDp + d)*HWsz + h*WWs + wq] = acc[gi] + b_off[gi];
    }
}

// ---------------- main conv: MODE 0 = deform conv, MODE 1 = conv2 ----------------
// block: 256 thr = 8 co_t (8 co each) x 32 sp_t (4h x 8wq x 7w)
// tile = 64 co x 4h x 56w ; grid = N*D*14 ; 2 CTAs/SM.
// warp = one co-group -> w LDS.128 is full-warp broadcast (1 crossbar cyc);
// per (ci,kh): 9 x LDS.64 feed 84 FFMA2 -> crossbar/fma ratio ~14%.
template<int MODE>
__global__ __launch_bounds__(256, 2)
void conv_main(const float* __restrict__ xin,
               const float* __restrict__ offp,
               const float* __restrict__ bias) {
    extern __shared__ char smraw[];
    ull*   xs   = (ull*)smraw;                        // [16 ci][6 hr][XPU] dup pairs
    float* ws   = (float*)(smraw + 16*6*XPU*8);       // [16 ci][9 tap][64 co]
    float* offs = (float*)(smraw + 16*6*XPU*8 + 9216*4); // [8][6][58] (MODE 0)

    const int tid = threadIdx.x;
    const int co_t = tid >> 5;              // warp id 0..7
    const int co0 = co_t * 8;
    const int sp_t = tid & 31;
    const int hh_loc = sp_t >> 3;           // 0..3
    const int ww0 = (sp_t & 7) * 7;         // 0..49
    const int bid = blockIdx.x;
    int b = bid;
    const int ht = b % 14; b /= 14;
    const int d = b % DDp; const int n = b / DDp;
    const int h0 = ht * 4;
    // co-resident CTAs (consecutive waves of 148) start 6 phases apart
    const int rot = ((bid / 148) & 1) * 6;

    const float* wT = (MODE == 0) ? g_wT1 : g_wT2;

    // acc[j*4+p] = f32x2 pair (co0+2p, co0+2p+1) for output w-index j (0..6)
    ull acc[28];
#pragma unroll
    for (int k = 0; k < 28; k++) acc[k] = 0ULL;

    if (MODE == 0) {
        for (int i = tid; i < 8*6*58; i += 256) {
            int wz = i % 58; int t = i / 58;
            int hr = t % 6;  int gi = t / 6;
            int hh = h0 - 1 + hr, ww = wz - 1;
            float v = 0.f;
            if ((unsigned)hh < HHs && (unsigned)ww < WWs)
                v = offp[((size_t)(n*GG + gi)*DDp + d)*HWsz + hh*WWs + ww];
            offs[(gi*6 + hr)*58 + wz] = v;
        }
    }

    for (int it = 0; it < 12; it++) {
        int idx = it + rot; if (idx >= 12) idx -= 12;
        const int kd = idx >> 2;           // 0..2
        const int phase = idx & 3;         // 0..3
        const int dd = d + kd - 1;
        const bool vd = (unsigned)dd < DDp;
        __syncthreads();      // prior compute done before xs/ws overwrite (covers offs 1st time)
        const int ci0 = phase * 16;
        // stage xs: 16 ci x 6 rows x 58 cols, dup pairs, pitch XPU
        for (int i = tid; i < 16*6*58; i += 256) {
            int wz = i % 58; int t = i / 58;
            int hr = t % 6;  int ci_l = t / 6;
            const int ci = ci0 + ci_l;
            int hh = h0 - 1 + hr, ww = wz - 1;
            float v = 0.f;
            if ((unsigned)hh < HHs && (unsigned)ww < WWs) {
                if (MODE == 0) {
                    // temporal deformable sampling: pos = d + off + (kd-1)
                    const float offv = offs[((ci >> 3)*6 + hr)*58 + wz];
                    const float pos = (offv + (float)d) + (float)(kd - 1);
                    const float f0 = floorf(pos);
                    const float frac = pos - f0;
                    const int i0 = (int)f0;
                    const float* base = xin + (size_t)n*CDHWsz + (size_t)ci*DHWsz + hh*WWs + ww;
                    const float v0 = ((unsigned)i0 < DDp) ? base[(size_t)i0*HWsz] : 0.f;
                    const float v1 = ((unsigned)(i0 + 1) < DDp) ? base[(size_t)(i0 + 1)*HWsz] : 0.f;
                    v = v0*(1.f - frac) + v1*frac;
                } else {
                    if (vd) {
                        const float y = g_y1[(size_t)n*CDHWsz + (size_t)ci*DHWsz + (size_t)dd*HWsz + hh*WWs + ww];
                        v = fmaxf(fmaf(g_a1[ci], y, g_b1[ci]), 0.f);   // BN1 + ReLU fused
                    }
                }
            }
            xs[(ci_l*6 + hr)*XPU + wz] = pack2(v, v);
        }
        // stage ws for same 16 ci (vectorized float4)
        for (int i4 = tid; i4 < 2304; i4 += 256) {
            const int co4 = (i4 & 15) * 4;
            const int t9 = (i4 >> 4) % 9;
            const int ci_l = i4 / 144;
            const float4 wv4 = *(const float4*)(wT + (size_t)(kd*9 + t9)*4096 + (ci0 + ci_l)*64 + co4);
            *(float4*)(ws + ci_l*576 + t9*64 + co4) = wv4;
        }
        __syncthreads();      // xs+ws ready

        for (int ci_l = 0; ci_l < 16; ci_l++) {
            const ull* xbase = xs + (ci_l*6 + hh_loc)*XPU + ww0;
            const float* wrow = ws + ci_l*576 + co0;
#pragma unroll
            for (int kh = 0; kh < 3; kh++) {
                // 4 co-pairs per kw tap; full-warp broadcast LDS.128 x2 per tap
                const ulonglong2 wA0 = *(const ulonglong2*)(wrow + (kh*3 + 0)*64);
                const ulonglong2 wB0 = *(const ulonglong2*)(wrow + (kh*3 + 0)*64 + 4);
                const ulonglong2 wA1 = *(const ulonglong2*)(wrow + (kh*3 + 1)*64);
                const ulonglong2 wB1 = *(const ulonglong2*)(wrow + (kh*3 + 1)*64 + 4);
                const ulonglong2 wA2 = *(const ulonglong2*)(wrow + (kh*3 + 2)*64);
                const ulonglong2 wB2 = *(const ulonglong2*)(wrow + (kh*3 + 2)*64 + 4);
                const ull* xrow = xbase + kh*XPU;
                ull xa = xrow[0];
                ull xb = xrow[1];
#pragma unroll
                for (int j = 0; j < 7; j++) {
                    const ull xc = xrow[j + 2];
                    ffma2(acc[j*4+0], wA0.x, xa);
                    ffma2(acc[j*4+1], wA0.y, xa);
                    ffma2(acc[j*4+2], wB0.x, xa);
                    ffma2(acc[j*4+3], wB0.y, xa);
                    ffma2(acc[j*4+0], wA1.x, xb);
                    ffma2(acc[j*4+1], wA1.y, xb);
                    ffma2(acc[j*4+2], wB1.x, xb);
                    ffma2(acc[j*4+3], wB1.y, xb);
                    ffma2(acc[j*4+0], wA2.x, xc);
                    ffma2(acc[j*4+1], wA2.y, xc);
                    ffma2(acc[j*4+2], wB2.x, xc);
                    ffma2(acc[j*4+3], wB2.y, xc);
                    xa = xb; xb = xc;   // renamed by full unroll (no MOVs emitted)
                }
            }
        }
    }

    // bias + store + fused BN stats (8 co per thread, 7 w outputs)
    float bv[8];
#pragma unroll
    for (int k = 0; k < 8; k++) bv[k] = (MODE == 1) ? bias[co0 + k] : 0.f;
    float* yout = (MODE == 0) ? g_y1 : g_y2;
    float s[8] = {0,0,0,0,0,0,0,0}, q[8] = {0,0,0,0,0,0,0,0};
    const int h = h0 + hh_loc;
#pragma unroll
    for (int j = 0; j < 7; j++) {
        const size_t base = (size_t)n*CDHWsz + (size_t)d*HWsz + h*WWs + (ww0 + j);
#pragma unroll
        for (int p = 0; p < 4; p++) {
            const float2 f = *(const float2*)&acc[j*4+p];
            const float u0 = f.x + bv[2*p];
            const float u1 = f.y + bv[2*p+1];
            yout[base + (size_t)(co0 + 2*p)*DHWsz]     = u0;
            yout[base + (size_t)(co0 + 2*p + 1)*DHWsz] = u1;
            s[2*p] += u0;   q[2*p] += u0*u0;
            s[2*p+1] += u1; q[2*p+1] += u1*u1;
        }
    }
    // full-warp reduce (all 32 lanes share the same 8-co group)
#pragma unroll
    for (int m = 1; m <= 16; m <<= 1) {
#pragma unroll
        for (int k = 0; k < 8; k++) {
            s[k] += __shfl_xor_sync(0xffffffffu, s[k], m);
            q[k] += __shfl_xor_sync(0xffffffffu, q[k], m);
        }
    }
    if (sp_t == 0) {
        float* gs = (MODE == 0) ? g_s1 : g_s2;
        float* gq = (MODE == 0) ? g_q1 : g_q2;
#pragma unroll
        for (int k = 0; k < 8; k++) {
            atomicAdd(&gs[co0 + k], s[k]);
            atomicAdd(&gq[co0 + k], q[k]);
        }
    }
}

// ---------------- BN finalize: a = gamma*rsqrt(var+eps), b = beta - a*mean ----------------
template<int WHICH>
__global__ void bn_finalize(const float* __restrict__ gamma, const float* __restrict__ beta) {
    const int c = threadIdx.x;
    const float* s = (WHICH == 0) ? g_s1 : g_s2;
    const float* q = (WHICH == 0) ? g_q1 : g_q2;
    float* a  = (WHICH == 0) ? g_a1 : g_a2;
    float* bo = (WHICH == 0) ? g_b1 : g_b2;
    const float mean = s[c] * (1.0f / CNTf);
    const float var  = q[c] * (1.0f / CNTf) - mean*mean;
    const float ai = gamma[c] * rsqrtf(var + 1e-5f);
    a[c] = ai;
    bo[c] = beta[c] - ai*mean;
}

// ---------------- epilogue: out = relu(bn2(y2) + x) ----------------
__global__ void finalize_out(const float* __restrict__ x, float* __restrict__ out) {
    const int i4 = blockIdx.x * blockDim.x + threadIdx.x;
    if (i4 >= OUT_ELEMS/4) return;
    const size_t i = (size_t)i4 * 4;
    const int c = (int)((i / DHWsz) & 63);
    const float a = g_a2[c], bb = g_b2[c];
    const float4 y  = *(const float4*)(g_y2 + i);
    const float4 xv = *(const float4*)(x + i);
    float4 r;
    r.x = fmaxf(fmaf(a, y.x, bb) + xv.x, 0.f);
    r.y = fmaxf(fmaf(a, y.y, bb) + xv.y, 0.f);
    r.z = fmaxf(fmaf(a, y.z, bb) + xv.z, 0.f);
    r.w = fmaxf(fmaf(a, y.w, bb) + xv.w, 0.f);
    *(float4*)(out + i) = r;
}

// ---------------- launch ----------------
extern "C" void kernel_launch(void* const* d_in, const int* in_sizes, int n_in,
                              void* d_out, int out_size) {
    const float* x     = (const float*)d_in[0];
    const float* w_off = (const float*)d_in[1];
    const float* b_off = (const float*)d_in[2];
    const float* w1    = (const float*)d_in[3];
    const float* w2    = (const float*)d_in[4];
    const float* b2    = (const float*)d_in[5];
    const float* g1    = (const float*)d_in[6];
    const float* be1   = (const float*)d_in[7];
    const float* g2    = (const float*)d_in[8];
    const float* be2   = (const float*)d_in[9];
    float* out = (float*)d_out;

    // off lives in d_out tail per tuple output (out, off); fall back to scratch if not.
    float* offdst = out + OUT_ELEMS;
    if (out_size < OUT_ELEMS + OFF_ELEMS) {
        void* p = nullptr;
        cudaGetSymbolAddress(&p, g_off);
        offdst = (float*)p;
    }

    const int SMEM_OFFK  = (64*6*64 + 2*512) * 4;                    // 102400
    const int SMEM_MAIN0 = 16*6*XPU*8 + 9216*4 + 8*6*58*4;           //  94080
    const int SMEM_MAIN1 = 16*6*XPU*8 + 9216*4;                      //  82944

    cudaFuncSetAttribute(conv_off_kernel, cudaFuncAttributeMaxDynamicSharedMemorySize, SMEM_OFFK);
    cudaFuncSetAttribute(conv_main<0>,    cudaFuncAttributeMaxDynamicSharedMemorySize, SMEM_MAIN0);
    cudaFuncSetAttribute(conv_main<1>,    cudaFuncAttributeMaxDynamicSharedMemorySize, SMEM_MAIN1);

    prep_kernel<<<432, 256>>>(w_off, w1, w2);          // idx 0
    conv_off_kernel<<<NN*DDp*14, 256, SMEM_OFFK>>>(x, b_off, offdst);  // idx 1
    dummy_kernel<<<1, 32>>>();                          // idx 2 (ncu shim)
    conv_main<0><<<NN*DDp*14, 256, SMEM_MAIN0>>>(x, offdst, b2);       // idx 3 <- ncu target
    bn_finalize<0><<<1, 64>>>(g1, be1);
    conv_main<1><<<NN*DDp*14, 256, SMEM_MAIN1>>>(x, offdst, b2);
    bn_finalize<1><<<1, 64>>>(g2, be2);
    finalize_out<<<(OUT_ELEMS/4 + 255)/256, 256>>>(x, out);
}